// round 17
// baseline (speedup 1.0000x reference)
#include <cuda_runtime.h>
#include <cuda_bf16.h>

// NeuralODE R17: 2 threads per trajectory. Each thread computes 32 of 64
// hidden units (4 packed groups, R14 math: 8-way shared rcp, exact 2^-15
// prescale, folded V); partial sums combined with two shfl.bfly adds per
// feval. 262144 threads -> 44 warps/SM (vs 27.7), attacking the diagnosed
// warp-starvation that pinned R14's issue at 73%.

#define NB    131072
#define NSEQ  150
#define ND    2
#define NH    64
#define NPRED 150
#define NSTEPS (NPRED - 1)

typedef unsigned long long u64;

__device__ __forceinline__ u64 pk(float a, float b) {
    u64 r; asm("mov.b64 %0, {%1, %2};" : "=l"(r) : "f"(a), "f"(b)); return r;
}
__device__ __forceinline__ float2 upk(u64 v) {
    float2 r; asm("mov.b64 {%0, %1}, %2;" : "=f"(r.x), "=f"(r.y) : "l"(v)); return r;
}
__device__ __forceinline__ u64 fma2(u64 a, u64 b, u64 c) {
    u64 d; asm("fma.rn.f32x2 %0, %1, %2, %3;" : "=l"(d) : "l"(a), "l"(b), "l"(c)); return d;
}
__device__ __forceinline__ u64 add2(u64 a, u64 b) {
    u64 d; asm("add.rn.f32x2 %0, %1, %2;" : "=l"(d) : "l"(a), "l"(b)); return d;
}
__device__ __forceinline__ u64 mul2(u64 a, u64 b) {
    u64 d; asm("mul.rn.f32x2 %0, %1, %2;" : "=l"(d) : "l"(a), "l"(b)); return d;
}
__device__ __forceinline__ float ex2f(float p) {
    float t; asm("ex2.approx.f32 %0, %1;" : "=f"(t) : "f"(p)); return t;
}
__device__ __forceinline__ float rcpf(float p) {
    float t; asm("rcp.approx.f32 %0, %1;" : "=f"(t) : "f"(p)); return t;
}

// Partial f(y): this thread's 4 groups (32 hidden units) starting at sWh/sBh/sVh.
// Returns UNreduced partial sums (no c; partner's half added via shfl outside).
__device__ __forceinline__ void feval_half(float y0, float y1,
                                           const ulonglong2* __restrict__ sWh,
                                           const ulonglong2* __restrict__ sBh,
                                           const ulonglong2* __restrict__ sVh,
                                           float& s0, float& s1) {
    const u64 y0p = pk(y0, y0);
    const u64 y1p = pk(y1, y1);
    const u64 c15 = 0x3800000038000000ull;   // {2^-15, 2^-15}
    u64 a0a = 0ull, a1a = 0ull;
    u64 a0b = 0ull, a1b = 0ull;
#pragma unroll 2
    for (int g = 0; g < 4; g++) {             // 8 hidden units per iteration
        ulonglong2 Wq0 = sWh[4 * g];
        ulonglong2 Wq1 = sWh[4 * g + 1];
        ulonglong2 Wq2 = sWh[4 * g + 2];
        ulonglong2 Wq3 = sWh[4 * g + 3];
        ulonglong2 Bg0 = sBh[2 * g];
        ulonglong2 Bg1 = sBh[2 * g + 1];
        u64 pA = fma2(y0p, Wq0.x, fma2(y1p, Wq0.y, Bg0.x));
        u64 pB = fma2(y0p, Wq1.x, fma2(y1p, Wq1.y, Bg0.y));
        u64 pC = fma2(y0p, Wq2.x, fma2(y1p, Wq2.y, Bg1.x));
        u64 pD = fma2(y0p, Wq3.x, fma2(y1p, Wq3.y, Bg1.y));
        float2 fa = upk(pA), fb = upk(pB), fc = upk(pC), fd = upk(pD);

        float t0 = ex2f(fminf(fa.x, 30.0f));
        float t1 = ex2f(fminf(fa.y, 30.0f));
        float t2 = ex2f(fminf(fb.x, 30.0f));
        float t3 = ex2f(fminf(fb.y, 30.0f));
        float t4 = ex2f(fminf(fc.x, 30.0f));
        float t5 = ex2f(fminf(fc.y, 30.0f));
        float t6 = ex2f(fminf(fd.x, 30.0f));
        float t7 = ex2f(fminf(fd.y, 30.0f));

        // u' = t*2^-15 + 2^-15 (exact); u' in [2^-15, 2^15+]
        u64 U01 = fma2(pk(t0, t1), c15, c15);
        u64 U23 = fma2(pk(t2, t3), c15, c15);
        u64 U45 = fma2(pk(t4, t5), c15, c15);
        u64 U67 = fma2(pk(t6, t7), c15, c15);

        // Packed 8-way shared reciprocal (1 MUFU rcp / 8 sigmoids);
        // 8-product in [2^-120, 2^120]: always normal fp32.
        u64 P1 = mul2(U01, U23);
        u64 P2 = mul2(U45, U67);
        u64 P  = mul2(P1, P2);
        float2 pf = upk(P);
        float rc  = rcpf(pf.x * pf.y);
        u64 Ss = pk(rc * pf.y, rc * pf.x);
        u64 T1 = mul2(Ss, P2);
        u64 T2 = mul2(Ss, P1);
        u64 r01 = mul2(T1, U23);
        u64 r23 = mul2(T1, U01);
        u64 r45 = mul2(T2, U67);
        u64 r67 = mul2(T2, U45);

        ulonglong2 V0 = sVh[4 * g];
        ulonglong2 V1 = sVh[4 * g + 1];
        ulonglong2 V2 = sVh[4 * g + 2];
        ulonglong2 V3 = sVh[4 * g + 3];
        a0a = fma2(r01, V0.x, a0a);
        a1a = fma2(r01, V0.y, a1a);
        a0b = fma2(r23, V1.x, a0b);
        a1b = fma2(r23, V1.y, a1b);
        a0a = fma2(r45, V2.x, a0a);
        a1a = fma2(r45, V2.y, a1a);
        a0b = fma2(r67, V3.x, a0b);
        a1b = fma2(r67, V3.y, a1b);
    }
    float2 f0 = upk(add2(a0a, a0b));
    float2 f1 = upk(add2(a1a, a1b));
    s0 = f0.x + f0.y;
    s1 = f1.x + f1.y;
}

__global__ void __launch_bounds__(128, 11)
neural_ode_kernel(const float* __restrict__ x,
                  const float* __restrict__ W1,
                  const float* __restrict__ b1,
                  const float* __restrict__ W2,
                  const float* __restrict__ b2,
                  float* __restrict__ out) {
    __shared__ alignas(16) float4 sWf[NH / 2];
    __shared__ alignas(16) float4 sVf[NH / 2];
    __shared__ alignas(16) float4 sBf[NH / 4];
    __shared__ float sc[2];

    const int tid = threadIdx.x;
    if (tid < NH / 2) {
        const float s  = 2.8853900817779268f;   // 2*log2(e)
        const float vs = -0.00006103515625f;    // -2^-14 (exact)
        int j = 2 * tid;
        sWf[tid] = make_float4(s * W1[j], s * W1[j + 1],
                               s * W1[NH + j], s * W1[NH + j + 1]);
        sVf[tid] = make_float4(vs * W2[2 * j], vs * W2[2 * (j + 1)],
                               vs * W2[2 * j + 1], vs * W2[2 * (j + 1) + 1]);
    }
    if (tid < NH / 4) {
        const float s = 2.8853900817779268f;
        int j = 4 * tid;
        sBf[tid] = make_float4(s * b1[j], s * b1[j + 1],
                               s * b1[j + 2], s * b1[j + 3]);
    }
    if (tid < 2) {
        float c = b2[tid];
        for (int j = 0; j < NH; j++) c += W2[2 * j + tid];
        sc[tid] = c;
    }
    __syncthreads();

    const long gt   = (long)blockIdx.x * blockDim.x + tid;  // global thread
    const long b    = gt >> 1;                               // trajectory
    const int  half = (int)(gt & 1);                         // 0: units 0-31, 1: 32-63

    // Per-half weight bases (4 groups of 8 units each)
    const ulonglong2* sWh = reinterpret_cast<const ulonglong2*>(sWf) + half * 16;
    const ulonglong2* sVh = reinterpret_cast<const ulonglong2*>(sVf) + half * 16;
    const ulonglong2* sBh = reinterpret_cast<const ulonglong2*>(sBf) + half * 8;

    const float c0 = sc[0];
    const float c1 = sc[1];

    const float2 yin = *(const float2*)(x + b * (long)(NSEQ * ND) + (NSEQ - 1) * ND);
    float y0 = yin.x;
    float y1 = yin.y;

    float2* ob = (float2*)(out + b * (long)(NPRED * ND));
    if (half == 0) ob[0] = make_float2(y0, y1);

    const float dt   = (float)(150.0 / 149.0);
    const float dt3  = dt * (1.0f / 3.0f);
    const float dt8  = dt * 0.125f;
    const float thrd = 1.0f / 3.0f;

#pragma unroll 1
    for (int st = 0; st < NSTEPS; st++) {
        float s0, s1;
        float k1x, k1y, k2x, k2y, k3x, k3y, k4x, k4y;

        feval_half(y0, y1, sWh, sBh, sVh, s0, s1);
        s0 += __shfl_xor_sync(0xffffffffu, s0, 1);
        s1 += __shfl_xor_sync(0xffffffffu, s1, 1);
        k1x = c0 + s0;  k1y = c1 + s1;

        feval_half(fmaf(dt3, k1x, y0), fmaf(dt3, k1y, y1), sWh, sBh, sVh, s0, s1);
        s0 += __shfl_xor_sync(0xffffffffu, s0, 1);
        s1 += __shfl_xor_sync(0xffffffffu, s1, 1);
        k2x = c0 + s0;  k2y = c1 + s1;

        feval_half(fmaf(dt, fmaf(-thrd, k1x, k2x), y0),
                   fmaf(dt, fmaf(-thrd, k1y, k2y), y1), sWh, sBh, sVh, s0, s1);
        s0 += __shfl_xor_sync(0xffffffffu, s0, 1);
        s1 += __shfl_xor_sync(0xffffffffu, s1, 1);
        k3x = c0 + s0;  k3y = c1 + s1;

        feval_half(fmaf(dt, (k1x - k2x) + k3x, y0),
                   fmaf(dt, (k1y - k2y) + k3y, y1), sWh, sBh, sVh, s0, s1);
        s0 += __shfl_xor_sync(0xffffffffu, s0, 1);
        s1 += __shfl_xor_sync(0xffffffffu, s1, 1);
        k4x = c0 + s0;  k4y = c1 + s1;

        y0 = fmaf(dt8, fmaf(3.0f, k2x + k3x, k1x + k4x), y0);
        y1 = fmaf(dt8, fmaf(3.0f, k2y + k3y, k1y + k4y), y1);

        if (half == 0) ob[st + 1] = make_float2(y0, y1);
    }
}

extern "C" void kernel_launch(void* const* d_in, const int* in_sizes, int n_in,
                              void* d_out, int out_size) {
    const float* x  = (const float*)d_in[0];
    const float* W1 = (const float*)d_in[1];
    const float* b1 = (const float*)d_in[2];
    const float* W2 = (const float*)d_in[3];
    const float* b2 = (const float*)d_in[4];
    float* out = (float*)d_out;

    const int block = 128;
    const int grid  = (NB * 2) / block;  // 262144 threads -> 2048 CTAs
    neural_ode_kernel<<<grid, block>>>(x, W1, b1, W2, b2, out);
}